// round 12
// baseline (speedup 1.0000x reference)
#include <cuda_runtime.h>
#include <cstdint>

#define B_ 4096
#define S_ 200
#define E_ 128
#define H_ 64
#define G_ 32
#define NT 384          // 12 warps

// ---- SMEM layout (bytes) --------------------------------------------------
#define KEYS_O   0          // 200 rows x 512B: fp32 staged -> in-place hi[0,256)+lo[256,512) bf16, xor-swizzled
#define W1T_O    102400     // 64 rows x 512B (hi|lo), resident
#define W2T_O    135168     // 32 rows x 256B (hi|lo), resident
#define QWALL_O  143360     // up to 37 iters x 64 f
#define SC_O     153600     // 200 f scores/weights
#define W3S_O    154576     // 32 f
#define B2S_O    154704     // 32 f
#define B3S_O    154832     // 1 f
#define MS0_O    154848     // mask slot 0
#define MS1_O    155648     // mask slot 1
#define AP_O     156448     // 6 x 128 f attended partials
#define SMEM_BYTES 159520

// prologue staging (inside KEYS region)
#define PW1_O    0
#define PW2_O    65536
#define PQ_O     73728
#define PB1_O    94208

static __device__ __forceinline__ uint32_t cvta_smem(const void* p) {
    uint32_t a;
    asm("{ .reg .u64 t; cvta.to.shared.u64 t, %1; cvt.u32.u64 %0, t; }" : "=r"(a) : "l"(p));
    return a;
}
static __device__ __forceinline__ uint32_t pk(float lo, float hi) {
    uint32_t r;
    asm("cvt.rn.bf16x2.f32 %0, %1, %2;" : "=r"(r) : "f"(hi), "f"(lo));
    return r;
}
static __device__ __forceinline__ float blo(uint32_t u) { return __uint_as_float(u << 16); }
static __device__ __forceinline__ float bhi(uint32_t u) { return __uint_as_float(u & 0xffff0000u); }

static __device__ __forceinline__ void ldsm4(uint32_t& r0, uint32_t& r1, uint32_t& r2, uint32_t& r3,
                                             uint32_t addr) {
    asm volatile("ldmatrix.sync.aligned.m8n8.x4.shared.b16 {%0,%1,%2,%3}, [%4];"
                 : "=r"(r0), "=r"(r1), "=r"(r2), "=r"(r3) : "r"(addr));
}
static __device__ __forceinline__ uint32_t lds32(uint32_t addr) {
    uint32_t v;
    asm volatile("ld.shared.u32 %0, [%1];" : "=r"(v) : "r"(addr));
    return v;
}
static __device__ __forceinline__ void mma_bf16(float* c, const uint32_t* a, uint32_t b0, uint32_t b1) {
    asm volatile("mma.sync.aligned.m16n8k16.row.col.f32.bf16.bf16.f32 "
                 "{%0,%1,%2,%3}, {%4,%5,%6,%7}, {%8,%9}, {%0,%1,%2,%3};"
                 : "+f"(c[0]), "+f"(c[1]), "+f"(c[2]), "+f"(c[3])
                 : "r"(a[0]), "r"(a[1]), "r"(a[2]), "r"(a[3]), "r"(b0), "r"(b1));
}

#define CPA(sm, g) asm volatile("cp.async.cg.shared.global [%0], [%1], 16;" :: "r"(sm), "l"(g))
#define CPC()      asm volatile("cp.async.commit_group;" ::: "memory")
#define CPW(n)     asm volatile("cp.async.wait_group %0;" :: "n"(n) : "memory")

__global__ __launch_bounds__(NT, 1)
void attn_persist_kernel(const float* __restrict__ query,
                         const float* __restrict__ keys,
                         const int*   __restrict__ mask,
                         const float* __restrict__ W1,
                         const float* __restrict__ b1,
                         const float* __restrict__ W2,
                         const float* __restrict__ b2,
                         const float* __restrict__ W3,
                         const float* __restrict__ b3,
                         float* __restrict__ out)
{
    extern __shared__ char smb[];
    const uint32_t sb = cvta_smem(smb);
    const int t    = threadIdx.x;
    const int warp = t >> 5;
    const int lane = t & 31;
    const int grid = gridDim.x;
    const int nb   = (B_ - blockIdx.x + grid - 1) / grid;

    // ================= Prologue =================
    {
        for (int i = t; i < 4096; i += NT) CPA(sb + PW1_O + i * 16, (const char*)W1 + i * 16);
        for (int i = t; i < 512; i += NT)  CPA(sb + PW2_O + i * 16, (const char*)W2 + i * 16);
        for (int j = t; j < nb * 32; j += NT) {
            const int bi = blockIdx.x + (j >> 5) * grid;
            CPA(sb + PQ_O + j * 16, (const char*)(query + (size_t)bi * E_) + (j & 31) * 16);
        }
        if (t < 16) CPA(sb + PB1_O + t * 16, (const char*)b1 + t * 16);
        if (t < 8)  CPA(sb + W3S_O + t * 16, (const char*)W3 + t * 16);
        if (t < 8)  CPA(sb + B2S_O + t * 16, (const char*)b2 + t * 16);
        CPC();
    }
    CPW(0);
    if (t == 0) ((float*)(smb + B3S_O))[0] = b3[0];
    __syncthreads();

    // W1T (rows 128..255 of W1) hi/lo bf16, swizzled
    {
        const float* stg = (const float*)(smb + PW1_O + 32768);
        for (int p = t; p < 4096; p += NT) {
            const int n  = p & 63;
            const int kp = p >> 6;
            const float a = stg[(2 * kp) * H_ + n];
            const float c = stg[(2 * kp + 1) * H_ + n];
            const uint32_t hu = pk(a, c);
            const uint32_t lu = pk(a - blo(hu), c - bhi(hu));
            char* dst = smb + W1T_O + n * 512 + (((uint32_t)(kp * 4)) ^ ((n & 7) << 4));
            *(uint32_t*)dst = hu;
            *(uint32_t*)(dst + 256) = lu;
        }
    }
    // W2T hi/lo bf16, swizzled
    {
        const float* stg2 = (const float*)(smb + PW2_O);
        for (int p = t; p < 1024; p += NT) {
            const int g  = p & 31;
            const int hp = p >> 5;
            const float a = stg2[(2 * hp) * G_ + g];
            const float c = stg2[(2 * hp + 1) * G_ + g];
            const uint32_t hu = pk(a, c);
            const uint32_t lu = pk(a - blo(hu), c - bhi(hu));
            char* dst = smb + W2T_O + g * 256 + (((uint32_t)(hp * 4)) ^ ((g & 7) << 4));
            *(uint32_t*)dst = hu;
            *(uint32_t*)(dst + 128) = lu;
        }
    }
    // qw[i][h] for all assigned b's (6-way i parallelism)
    {
        const float* w1top = (const float*)(smb + PW1_O);
        const float* b1f   = (const float*)(smb + PB1_O);
        const int h    = t & 63;
        const int isub = t >> 6;                // 0..5
        for (int i0 = 0; i0 < nb; i0 += 6) {
            const int i = i0 + isub;
            if (i < nb) {
                const float* q = (const float*)(smb + PQ_O) + i * 128;
                float s = b1f[h];
                #pragma unroll 8
                for (int e = 0; e < 128; ++e) s = fmaf(q[e], w1top[e * 64 + h], s);
                ((float*)(smb + QWALL_O))[i * 64 + h] = s;
            }
        }
    }
    __syncthreads();

    // first keys + mask fetch (all threads)
    {
        const char* gk = (const char*)keys + (size_t)blockIdx.x * (S_ * E_ * 4);
        for (int i = t; i < 6400; i += NT) CPA(sb + KEYS_O + i * 16, gk + (size_t)i * 16);
        if (t < 50) CPA(sb + MS0_O + t * 16, (const char*)(mask + (size_t)blockIdx.x * S_) + t * 16);
        CPC();
    }

    const int r0 = lane >> 2;
    const int cb = (lane & 3) * 2;

    // ================= Main loop =================
    for (int it = 0; it < nb; ++it) {
        const int b = blockIdx.x + it * grid;
        CPW(0);              // per-thread wait on own prefetch groups
        __syncthreads();

        float* scf = (float*)(smb + SC_O);

        // warp 7: prefetch next mask (double-buffered slot)
        if (warp == 7 && it + 1 < nb) {
            const int bn = b + grid;
            const uint32_t msn = sb + (((it + 1) & 1) ? MS1_O : MS0_O);
            #pragma unroll
            for (int c = lane; c < 50; c += 32)
                CPA(msn + c * 16, (const char*)(mask + (size_t)bn * S_) + c * 16);
            CPC();
        }

        if (warp < 7) {
            const int m0 = warp * 32;                 // 0,32,...,192
            const bool two = (warp < 6);              // warp 6: single m-tile (rows 192-207)

            // ---- warp-local convert: own real rows only ----
            {
                const int rend = (m0 + 32 < S_) ? m0 + 32 : S_;
                for (int r = m0; r < rend; ++r) {
                    const uint32_t rowb = (uint32_t)(r * 512);
                    const float4 v = *(const float4*)(smb + rowb + lane * 16);
                    const uint32_t h01 = pk(v.x, v.y), h23 = pk(v.z, v.w);
                    const uint32_t l01 = pk(v.x - blo(h01), v.y - bhi(h01));
                    const uint32_t l23 = pk(v.z - blo(h23), v.w - bhi(h23));
                    const uint32_t xo = (uint32_t)((r & 7) << 4);
                    *(uint64_t*)(smb + rowb + ((lane * 8) ^ xo))       = (uint64_t)h01 | ((uint64_t)h23 << 32);
                    *(uint64_t*)(smb + rowb + 256 + ((lane * 8) ^ xo)) = (uint64_t)l01 | ((uint64_t)l23 << 32);
                }
            }
            __syncwarp();

            // ---- Layer 1: two m-tiles share every B fragment load ----
            float acc[2][8][4];
            #pragma unroll
            for (int mt = 0; mt < 2; ++mt)
                #pragma unroll
                for (int n = 0; n < 8; ++n)
                    #pragma unroll
                    for (int j = 0; j < 4; ++j) acc[mt][n][j] = 0.f;

            const uint32_t axor   = (uint32_t)((lane & 7) << 4);
            const uint32_t ag16   = (uint32_t)((lane >> 4) << 4);
            const uint32_t a0base = sb + KEYS_O + (m0 + (lane & 15)) * 512;
            const uint32_t a1base = a0base + 16 * 512;      // warp6: reads into W1T (harmless)
            const uint32_t bxor   = (uint32_t)((lane >> 2) << 4);
            const uint32_t bl4    = (uint32_t)((lane & 3) * 4);
            const uint32_t brow0  = sb + W1T_O + (lane >> 2) * 512;

            #pragma unroll
            for (int k = 0; k < 8; ++k) {
                uint32_t ah0[4], al0[4], ah1[4], al1[4];
                const uint32_t ac = ((uint32_t)(k * 32) + ag16) ^ axor;
                ldsm4(ah0[0], ah0[1], ah0[2], ah0[3], a0base + ac);
                ldsm4(al0[0], al0[1], al0[2], al0[3], a0base + 256 + ac);
                if (two) {
                    ldsm4(ah1[0], ah1[1], ah1[2], ah1[3], a1base + ac);
                    ldsm4(al1[0], al1[1], al1[2], al1[3], a1base + 256 + ac);
                }
                const uint32_t c0 = ((uint32_t)(k * 32) ^ bxor) + bl4;
                const uint32_t c1 = ((uint32_t)(k * 32 + 16) ^ bxor) + bl4;
                #pragma unroll
                for (int n = 0; n < 8; ++n) {
                    const uint32_t brow = brow0 + n * (8 * 512);
                    const uint32_t bh0 = lds32(brow + c0);
                    const uint32_t bh1 = lds32(brow + c1);
                    const uint32_t bl0 = lds32(brow + 256 + c0);
                    const uint32_t bl1 = lds32(brow + 256 + c1);
                    mma_bf16(acc[0][n], ah0, bh0, bh1);
                    mma_bf16(acc[0][n], ah0, bl0, bl1);
                    mma_bf16(acc[0][n], al0, bh0, bh1);
                    if (two) {
                        mma_bf16(acc[1][n], ah1, bh0, bh1);
                        mma_bf16(acc[1][n], ah1, bl0, bl1);
                        mma_bf16(acc[1][n], al1, bh0, bh1);
                    }
                }
            }

            // ---- EARLY warp-local prefetch of next b's OWN key rows ----
            if (it + 1 < nb) {
                const int bn = b + grid;
                const int nrows = (m0 + 32 <= S_) ? 32 : (S_ - m0);   // warp 6: 8
                const char* gk = (const char*)keys +
                                 ((size_t)bn * (S_ * E_) + (size_t)m0 * E_) * 4;
                #pragma unroll 4
                for (int c = lane; c < nrows * 32; c += 32)
                    CPA(sb + KEYS_O + m0 * 512 + c * 16, gk + (size_t)c * 16);
                CPC();
            }

            // ---- per m-tile: epilogue -> layer 2 -> layer 3 ----
            const float* qwf = (const float*)(smb + QWALL_O) + it * 64;
            const float* b2f = (const float*)(smb + B2S_O);
            const float* w3f = (const float*)(smb + W3S_O);
            const float  b3v = ((const float*)(smb + B3S_O))[0];
            const int*   msk = (const int*)(smb + ((it & 1) ? MS1_O : MS0_O));
            const uint32_t b2row0 = sb + W2T_O + (lane >> 2) * 256;
            const int ntiles = two ? 2 : 1;

            for (int mt = 0; mt < ntiles; ++mt) {
                uint32_t ahf[4][4], alf[4][4];
                #pragma unroll
                for (int kt = 0; kt < 4; ++kt) {
                    #pragma unroll
                    for (int half = 0; half < 2; ++half) {
                        const int n = 2 * kt + half;
                        const int c = n * 8 + cb;
                        const float qa = qwf[c], qb = qwf[c + 1];
                        const float v0 = fmaxf(acc[mt][n][0] + qa, 0.f);   // fmaxf sanitizes NaN rows
                        const float v1 = fmaxf(acc[mt][n][1] + qb, 0.f);
                        const float v2 = fmaxf(acc[mt][n][2] + qa, 0.f);
                        const float v3 = fmaxf(acc[mt][n][3] + qb, 0.f);
                        const uint32_t h01 = pk(v0, v1), h23 = pk(v2, v3);
                        ahf[kt][2 * half]     = h01;
                        ahf[kt][2 * half + 1] = h23;
                        alf[kt][2 * half]     = pk(v0 - blo(h01), v1 - bhi(h01));
                        alf[kt][2 * half + 1] = pk(v2 - blo(h23), v3 - bhi(h23));
                    }
                }

                float acc2[4][4];
                #pragma unroll
                for (int n = 0; n < 4; ++n)
                    #pragma unroll
                    for (int j = 0; j < 4; ++j) acc2[n][j] = 0.f;

                #pragma unroll
                for (int kt = 0; kt < 4; ++kt) {
                    const uint32_t c0 = ((uint32_t)(kt * 32) ^ bxor) + bl4;
                    const uint32_t c1 = ((uint32_t)(kt * 32 + 16) ^ bxor) + bl4;
                    #pragma unroll
                    for (int n = 0; n < 4; ++n) {
                        const uint32_t brow = b2row0 + n * (8 * 256);
                        const uint32_t bh0 = lds32(brow + c0);
                        const uint32_t bh1 = lds32(brow + c1);
                        const uint32_t bl0 = lds32(brow + 128 + c0);
                        const uint32_t bl1 = lds32(brow + 128 + c1);
                        mma_bf16(acc2[n], ahf[kt], bh0, bh1);
                        mma_bf16(acc2[n], ahf[kt], bl0, bl1);
                        mma_bf16(acc2[n], alf[kt], bh0, bh1);
                    }
                }

                float p0 = 0.f, p8 = 0.f;
                #pragma unroll
                for (int n = 0; n < 4; ++n) {
                    const int c = n * 8 + cb;
                    const float w3a = w3f[c], w3b = w3f[c + 1];
                    const float ba = b2f[c],  bb = b2f[c + 1];
                    p0 = fmaf(fmaxf(acc2[n][0] + ba, 0.f), w3a,
                         fmaf(fmaxf(acc2[n][1] + bb, 0.f), w3b, p0));
                    p8 = fmaf(fmaxf(acc2[n][2] + ba, 0.f), w3a,
                         fmaf(fmaxf(acc2[n][3] + bb, 0.f), w3b, p8));
                }
                p0 += __shfl_xor_sync(0xffffffffu, p0, 1);
                p0 += __shfl_xor_sync(0xffffffffu, p0, 2);
                p8 += __shfl_xor_sync(0xffffffffu, p8, 1);
                p8 += __shfl_xor_sync(0xffffffffu, p8, 2);
                if ((lane & 3) == 0) {
                    const int rowA = m0 + 16 * mt + r0;
                    const int rowB = rowA + 8;
                    if (rowA < S_) {
                        float sc = p0 + b3v;
                        if (msk[rowA] == 0) sc = -1e9f;
                        scf[rowA] = sc;
                    }
                    if (rowB < S_) {
                        float sc = p8 + b3v;
                        if (msk[rowB] == 0) sc = -1e9f;
                        scf[rowB] = sc;
                    }
                }
            }
        }
        __syncthreads();   // scores complete

        // ---- Softmax: single warp (11), weights -> scf + global ----
        if (warp == 11) {
            float v[7];
            float mx = -3e38f;
            #pragma unroll
            for (int j = 0; j < 7; ++j) {
                const int s = lane + 32 * j;
                v[j] = (s < S_) ? scf[s] : -3e38f;
                mx = fmaxf(mx, v[j]);
            }
            #pragma unroll
            for (int o = 16; o; o >>= 1) mx = fmaxf(mx, __shfl_xor_sync(0xffffffffu, mx, o));
            float sum = 0.f;
            #pragma unroll
            for (int j = 0; j < 7; ++j) {
                const int s = lane + 32 * j;
                if (s < S_) { v[j] = expf(v[j] - mx); sum += v[j]; }
            }
            #pragma unroll
            for (int o = 16; o; o >>= 1) sum += __shfl_xor_sync(0xffffffffu, sum, o);
            const float inv = 1.0f / sum;
            float* out_w = out + (size_t)B_ * E_ + (size_t)b * S_;
            #pragma unroll
            for (int j = 0; j < 7; ++j) {
                const int s = lane + 32 * j;
                if (s < S_) {
                    const float w = v[j] * inv;
                    scf[s] = w;
                    out_w[s] = w;
                }
            }
        }
        __syncthreads();

        // ---- attended[e]: 6 partitions x ~34 s, float2 global loads ----
        {
            const int e2 = t & 63;          // float2 column (e = 2*e2, 2*e2+1)
            const int pp = t >> 6;          // 0..5
            const float2* kg = (const float2*)(keys + (size_t)b * (S_ * E_)) + e2;
            float a0 = 0.f, a1 = 0.f;
            const int sbeg = pp * 33;
            const int send = (pp == 5) ? S_ : sbeg + 33;
            #pragma unroll 8
            for (int s = sbeg; s < send; ++s) {
                const float2 kv = kg[(size_t)s * 64];
                const float w = scf[s];
                a0 = fmaf(w, kv.x, a0);
                a1 = fmaf(w, kv.y, a1);
            }
            float2* apf = (float2*)(smb + AP_O);
            apf[pp * 64 + e2] = make_float2(a0, a1);
        }
        __syncthreads();
        if (t < E_) {
            const float* apf = (const float*)(smb + AP_O);
            float a = 0.f;
            #pragma unroll
            for (int g = 0; g < 6; ++g) a += apf[g * 128 + t];
            out[(size_t)b * E_ + t] = a;
        }
        // next-iter loop-top __syncthreads orders AP/scf reuse
    }
}

extern "C" void kernel_launch(void* const* d_in, const int* in_sizes, int n_in,
                              void* d_out, int out_size) {
    const float* query = (const float*)d_in[0];
    const float* keys  = (const float*)d_in[1];
    const int*   mask  = (const int*)d_in[2];
    const float* W1    = (const float*)d_in[3];
    const float* b1    = (const float*)d_in[4];
    const float* W2    = (const float*)d_in[5];
    const float* b2    = (const float*)d_in[6];
    const float* W3    = (const float*)d_in[7];
    const float* b3    = (const float*)d_in[8];
    float* out = (float*)d_out;

    int nsm = 148;
    cudaDeviceGetAttribute(&nsm, cudaDevAttrMultiProcessorCount, 0);
    if (nsm < 112)  nsm = 112;
    if (nsm > 1024) nsm = 1024;

    cudaFuncSetAttribute(attn_persist_kernel,
                         cudaFuncAttributeMaxDynamicSharedMemorySize, SMEM_BYTES);
    attn_persist_kernel<<<nsm, NT, SMEM_BYTES>>>(query, keys, mask, W1, b1, W2, b2, W3, b3, out);
}

// round 13
// speedup vs baseline: 1.2456x; 1.2456x over previous
#include <cuda_runtime.h>
#include <cstdint>

#define B_ 4096
#define S_ 200
#define E_ 128
#define H_ 64
#define G_ 32

// ---- SMEM layout (bytes) --------------------------------------------------
#define KEYS_O   0          // 200 rows x 512B: fp32 staged -> in-place hi[0,256)+lo[256,512) bf16, xor-swizzled
#define W1T_O    102400     // 64 rows x 512B (hi|lo), resident
#define W2T_O    135168     // 32 rows x 256B (hi|lo), resident
#define QWALL_O  143360     // up to 40 iters x 64 f
#define SC_O     153600     // 200 f scores / unnormalized exp
#define RED_O    154432     // 16 f warp partial sums
#define W3S_O    154576     // 32 f
#define B2S_O    154704     // 32 f
#define B3S_O    154832     // 1 f
#define MS0_O    154848     // mask slot 0
#define MS1_O    155648     // mask slot 1
#define AP_O     156448     // 8 x 128 f attended partials (4KB)
#define SMEM_BYTES 160768

// prologue staging (inside KEYS region)
#define PW1_O    0
#define PW2_O    65536
#define PQ_O     73728
#define PB1_O    94208

static __device__ __forceinline__ uint32_t cvta_smem(const void* p) {
    uint32_t a;
    asm("{ .reg .u64 t; cvta.to.shared.u64 t, %1; cvt.u32.u64 %0, t; }" : "=r"(a) : "l"(p));
    return a;
}
static __device__ __forceinline__ uint32_t pk(float lo, float hi) {
    uint32_t r;
    asm("cvt.rn.bf16x2.f32 %0, %1, %2;" : "=r"(r) : "f"(hi), "f"(lo));
    return r;
}
static __device__ __forceinline__ float blo(uint32_t u) { return __uint_as_float(u << 16); }
static __device__ __forceinline__ float bhi(uint32_t u) { return __uint_as_float(u & 0xffff0000u); }

static __device__ __forceinline__ void ldsm4(uint32_t& r0, uint32_t& r1, uint32_t& r2, uint32_t& r3,
                                             uint32_t addr) {
    asm volatile("ldmatrix.sync.aligned.m8n8.x4.shared.b16 {%0,%1,%2,%3}, [%4];"
                 : "=r"(r0), "=r"(r1), "=r"(r2), "=r"(r3) : "r"(addr));
}
static __device__ __forceinline__ uint32_t lds32(uint32_t addr) {
    uint32_t v;
    asm volatile("ld.shared.u32 %0, [%1];" : "=r"(v) : "r"(addr));
    return v;
}
static __device__ __forceinline__ void mma_bf16(float* c, const uint32_t* a, uint32_t b0, uint32_t b1) {
    asm volatile("mma.sync.aligned.m16n8k16.row.col.f32.bf16.bf16.f32 "
                 "{%0,%1,%2,%3}, {%4,%5,%6,%7}, {%8,%9}, {%0,%1,%2,%3};"
                 : "+f"(c[0]), "+f"(c[1]), "+f"(c[2]), "+f"(c[3])
                 : "r"(a[0]), "r"(a[1]), "r"(a[2]), "r"(a[3]), "r"(b0), "r"(b1));
}

#define CPA(sm, g) asm volatile("cp.async.cg.shared.global [%0], [%1], 16;" :: "r"(sm), "l"(g))
#define CPC()      asm volatile("cp.async.commit_group;" ::: "memory")
#define CPW(n)     asm volatile("cp.async.wait_group %0;" :: "n"(n) : "memory")

// convert one key row r: fp32 (512B) -> hi/lo bf16, in place, swizzled
#define CONV_ROW(r) do { \
    const uint32_t rowb = (uint32_t)((r) * 512); \
    const float4 v = *(const float4*)(smb + rowb + lane * 16); \
    const uint32_t h01 = pk(v.x, v.y), h23 = pk(v.z, v.w); \
    const uint32_t l01 = pk(v.x - blo(h01), v.y - bhi(h01)); \
    const uint32_t l23 = pk(v.z - blo(h23), v.w - bhi(h23)); \
    const uint32_t xo = (uint32_t)(((r) & 7) << 4); \
    *(uint64_t*)(smb + rowb + ((lane * 8) ^ xo))       = (uint64_t)h01 | ((uint64_t)h23 << 32); \
    *(uint64_t*)(smb + rowb + 256 + ((lane * 8) ^ xo)) = (uint64_t)l01 | ((uint64_t)l23 << 32); \
} while (0)

__global__ __launch_bounds__(512, 1)
void attn_persist_kernel(const float* __restrict__ query,
                         const float* __restrict__ keys,
                         const int*   __restrict__ mask,
                         const float* __restrict__ W1,
                         const float* __restrict__ b1,
                         const float* __restrict__ W2,
                         const float* __restrict__ b2,
                         const float* __restrict__ W3,
                         const float* __restrict__ b3,
                         float* __restrict__ out)
{
    extern __shared__ char smb[];
    const uint32_t sb = cvta_smem(smb);
    const int t    = threadIdx.x;
    const int warp = t >> 5;
    const int lane = t & 31;
    const int grid = gridDim.x;
    const int nb   = (B_ - blockIdx.x + grid - 1) / grid;

    // ================= Prologue =================
    {
        #pragma unroll 4
        for (int i = t; i < 4096; i += 512) CPA(sb + PW1_O + i * 16, (const char*)W1 + i * 16);
        CPA(sb + PW2_O + t * 16, (const char*)W2 + t * 16);
        for (int j = t; j < nb * 32; j += 512) {
            const int bi = blockIdx.x + (j >> 5) * grid;
            CPA(sb + PQ_O + j * 16, (const char*)(query + (size_t)bi * E_) + (j & 31) * 16);
        }
        if (t < 16) CPA(sb + PB1_O + t * 16, (const char*)b1 + t * 16);
        if (t < 8)  CPA(sb + W3S_O + t * 16, (const char*)W3 + t * 16);
        if (t < 8)  CPA(sb + B2S_O + t * 16, (const char*)b2 + t * 16);
        CPC();
    }
    CPW(0);
    if (t == 0) ((float*)(smb + B3S_O))[0] = b3[0];
    __syncthreads();

    // W1T (rows 128..255 of W1) hi/lo bf16, swizzled
    {
        const float* stg = (const float*)(smb + PW1_O + 32768);
        #pragma unroll
        for (int p = t; p < 4096; p += 512) {
            const int n  = p & 63;
            const int kp = p >> 6;
            const float a = stg[(2 * kp) * H_ + n];
            const float c = stg[(2 * kp + 1) * H_ + n];
            const uint32_t hu = pk(a, c);
            const uint32_t lu = pk(a - blo(hu), c - bhi(hu));
            char* dst = smb + W1T_O + n * 512 + (((uint32_t)(kp * 4)) ^ ((n & 7) << 4));
            *(uint32_t*)dst = hu;
            *(uint32_t*)(dst + 256) = lu;
        }
    }
    // W2T hi/lo bf16, swizzled
    {
        const float* stg2 = (const float*)(smb + PW2_O);
        #pragma unroll
        for (int p = t; p < 1024; p += 512) {
            const int g  = p & 31;
            const int hp = p >> 5;
            const float a = stg2[(2 * hp) * G_ + g];
            const float c = stg2[(2 * hp + 1) * G_ + g];
            const uint32_t hu = pk(a, c);
            const uint32_t lu = pk(a - blo(hu), c - bhi(hu));
            char* dst = smb + W2T_O + g * 256 + (((uint32_t)(hp * 4)) ^ ((g & 7) << 4));
            *(uint32_t*)dst = hu;
            *(uint32_t*)(dst + 128) = lu;
        }
    }
    // qw[i][h] for all assigned b's
    {
        const float* w1top = (const float*)(smb + PW1_O);
        const float* b1f   = (const float*)(smb + PB1_O);
        const int h    = t & 63;
        const int isub = t >> 6;
        for (int i0 = 0; i0 < nb; i0 += 8) {
            const int i = i0 + isub;
            if (i < nb) {
                const float* q = (const float*)(smb + PQ_O) + i * 128;
                float s = b1f[h];
                #pragma unroll 8
                for (int e = 0; e < 128; ++e) s = fmaf(q[e], w1top[e * 64 + h], s);
                ((float*)(smb + QWALL_O))[i * 64 + h] = s;
            }
        }
    }
    __syncthreads();

    // first keys + mask fetch (all threads)
    {
        const char* gk = (const char*)keys + (size_t)blockIdx.x * (S_ * E_ * 4);
        for (int i = t; i < 6400; i += 512) CPA(sb + KEYS_O + i * 16, gk + (size_t)i * 16);
        if (t < 50) CPA(sb + MS0_O + t * 16, (const char*)(mask + (size_t)blockIdx.x * S_) + t * 16);
        CPC();
    }

    const int r0 = lane >> 2;
    const int cb = (lane & 3) * 2;

    // ================= Main loop =================
    for (int it = 0; it < nb; ++it) {
        const int b = blockIdx.x + it * grid;
        CPW(0);              // per-thread: waits only this thread's prefetch groups
        __syncthreads();

        float* scf = (float*)(smb + SC_O);

        // warp 13: prefetch next mask (double-buffered slot; 50 chunks over 32 lanes)
        if (warp == 13 && it + 1 < nb) {
            const int bn = b + grid;
            const uint32_t msn = sb + (((it + 1) & 1) ? MS1_O : MS0_O);
            #pragma unroll
            for (int c = lane; c < 50; c += 32)
                CPA(msn + c * 16, (const char*)(mask + (size_t)bn * S_) + c * 16);
            CPC();
        }

        if (warp < 13) {
            const int m0 = warp * 16;

            // ---- warp-local convert, compile-time unrolled for load batching ----
            if (m0 + 16 <= S_) {
                #pragma unroll
                for (int i = 0; i < 16; ++i) CONV_ROW(m0 + i);
            } else {
                #pragma unroll
                for (int i = 0; i < 8; ++i) CONV_ROW(m0 + i);   // warp 12: rows 192-199
            }
            __syncwarp();

            // ---- Layer 1: acc = keys @ W1bot (3-product split bf16) ----
            float acc[8][4];
            #pragma unroll
            for (int n = 0; n < 8; ++n)
                #pragma unroll
                for (int j = 0; j < 4; ++j) acc[n][j] = 0.f;

            const uint32_t axor   = (uint32_t)((lane & 7) << 4);
            const uint32_t a_base = sb + KEYS_O + (m0 + (lane & 15)) * 512;
            const uint32_t ag16   = (uint32_t)((lane >> 4) << 4);
            const uint32_t bxor   = (uint32_t)((lane >> 2) << 4);
            const uint32_t bl4    = (uint32_t)((lane & 3) * 4);
            const uint32_t brow0  = sb + W1T_O + (lane >> 2) * 512;

            #pragma unroll
            for (int k = 0; k < 8; ++k) {
                uint32_t ah[4], al[4];
                const uint32_t ac = ((uint32_t)(k * 32) + ag16) ^ axor;
                ldsm4(ah[0], ah[1], ah[2], ah[3], a_base + ac);
                ldsm4(al[0], al[1], al[2], al[3], a_base + 256 + ac);
                const uint32_t c0 = ((uint32_t)(k * 32) ^ bxor) + bl4;
                const uint32_t c1 = ((uint32_t)(k * 32 + 16) ^ bxor) + bl4;
                #pragma unroll
                for (int n = 0; n < 8; ++n) {
                    const uint32_t brow = brow0 + n * (8 * 512);
                    const uint32_t bh0 = lds32(brow + c0);
                    const uint32_t bh1 = lds32(brow + c1);
                    const uint32_t bl0 = lds32(brow + 256 + c0);
                    const uint32_t bl1 = lds32(brow + 256 + c1);
                    mma_bf16(acc[n], ah, bh0, bh1);
                    mma_bf16(acc[n], ah, bl0, bl1);
                    mma_bf16(acc[n], al, bh0, bh1);
                }
            }

            // ---- EARLY warp-local prefetch of next b's OWN key rows ----
            if (it + 1 < nb) {
                const int bn = b + grid;
                const int nrows = (m0 + 16 <= S_) ? 16 : (S_ - m0);   // warp 12: 8
                const char* gk = (const char*)keys +
                                 ((size_t)bn * (S_ * E_) + (size_t)m0 * E_) * 4;
                #pragma unroll 4
                for (int c = lane; c < nrows * 32; c += 32)
                    CPA(sb + KEYS_O + m0 * 512 + c * 16, gk + (size_t)c * 16);
                CPC();
            }

            // ---- epilogue: +qw, relu, split hi/lo -> A-fragments for layer 2 ----
            uint32_t ahf[4][4], alf[4][4];
            const float* qwf = (const float*)(smb + QWALL_O) + it * 64;
            #pragma unroll
            for (int kt = 0; kt < 4; ++kt) {
                #pragma unroll
                for (int half = 0; half < 2; ++half) {
                    const int n = 2 * kt + half;
                    const int c = n * 8 + cb;
                    const float qa = qwf[c], qb = qwf[c + 1];
                    const float v0 = fmaxf(acc[n][0] + qa, 0.f);
                    const float v1 = fmaxf(acc[n][1] + qb, 0.f);
                    const float v2 = fmaxf(acc[n][2] + qa, 0.f);
                    const float v3 = fmaxf(acc[n][3] + qb, 0.f);
                    const uint32_t h01 = pk(v0, v1), h23 = pk(v2, v3);
                    ahf[kt][2 * half]     = h01;
                    ahf[kt][2 * half + 1] = h23;
                    alf[kt][2 * half]     = pk(v0 - blo(h01), v1 - bhi(h01));
                    alf[kt][2 * half + 1] = pk(v2 - blo(h23), v3 - bhi(h23));
                }
            }

            // ---- Layer 2 (register A) ----
            float acc2[4][4];
            #pragma unroll
            for (int n = 0; n < 4; ++n)
                #pragma unroll
                for (int j = 0; j < 4; ++j) acc2[n][j] = 0.f;

            const uint32_t b2row0 = sb + W2T_O + (lane >> 2) * 256;
            #pragma unroll
            for (int kt = 0; kt < 4; ++kt) {
                const uint32_t c0 = ((uint32_t)(kt * 32) ^ bxor) + bl4;
                const uint32_t c1 = ((uint32_t)(kt * 32 + 16) ^ bxor) + bl4;
                #pragma unroll
                for (int n = 0; n < 4; ++n) {
                    const uint32_t brow = b2row0 + n * (8 * 256);
                    const uint32_t bh0 = lds32(brow + c0);
                    const uint32_t bh1 = lds32(brow + c1);
                    const uint32_t bl0 = lds32(brow + 128 + c0);
                    const uint32_t bl1 = lds32(brow + 128 + c1);
                    mma_bf16(acc2[n], ahf[kt], bh0, bh1);
                    mma_bf16(acc2[n], ahf[kt], bl0, bl1);
                    mma_bf16(acc2[n], alf[kt], bh0, bh1);
                }
            }

            // ---- Layer 3: register dot + shfl ----
            const float* b2f = (const float*)(smb + B2S_O);
            const float* w3f = (const float*)(smb + W3S_O);
            float p0 = 0.f, p8 = 0.f;
            #pragma unroll
            for (int n = 0; n < 4; ++n) {
                const int c = n * 8 + cb;
                const float w3a = w3f[c], w3b = w3f[c + 1];
                const float ba = b2f[c],  bb = b2f[c + 1];
                p0 = fmaf(fmaxf(acc2[n][0] + ba, 0.f), w3a,
                     fmaf(fmaxf(acc2[n][1] + bb, 0.f), w3b, p0));
                p8 = fmaf(fmaxf(acc2[n][2] + ba, 0.f), w3a,
                     fmaf(fmaxf(acc2[n][3] + bb, 0.f), w3b, p8));
            }
            p0 += __shfl_xor_sync(0xffffffffu, p0, 1);
            p0 += __shfl_xor_sync(0xffffffffu, p0, 2);
            p8 += __shfl_xor_sync(0xffffffffu, p8, 1);
            p8 += __shfl_xor_sync(0xffffffffu, p8, 2);
            if ((lane & 3) == 0) {
                const int rowA = m0 + r0;
                const int rowB = rowA + 8;
                const float b3v = ((const float*)(smb + B3S_O))[0];
                const int* msk = (const int*)(smb + ((it & 1) ? MS1_O : MS0_O));
                if (rowA < S_) {
                    float sc = p0 + b3v;
                    if (msk[rowA] == 0) sc = -1e9f;
                    scf[rowA] = sc;
                }
                if (rowB < S_) {
                    float sc = p8 + b3v;
                    if (msk[rowB] == 0) sc = -1e9f;
                    scf[rowB] = sc;
                }
            }
        }
        __syncthreads();   // scores complete

        // ---- Distributed softmax: every warp computes max redundantly, then
        //      exponentiates a 13-element slice; scf holds UNNORMALIZED exp. ----
        {
            float mx = -3e38f;
            #pragma unroll
            for (int j = 0; j < 7; ++j) {
                const int s = lane + 32 * j;
                if (s < S_) mx = fmaxf(mx, scf[s]);
            }
            #pragma unroll
            for (int o = 16; o; o >>= 1) mx = fmaxf(mx, __shfl_xor_sync(0xffffffffu, mx, o));

            float e = 0.f;
            const int s = warp * 13 + lane;
            if (lane < 13 && s < S_) {
                e = __expf(scf[s] - mx);
                scf[s] = e;
            }
            #pragma unroll
            for (int o = 16; o; o >>= 1) e += __shfl_xor_sync(0xffffffffu, e, o);
            if (lane == 0) ((float*)(smb + RED_O))[warp] = e;
        }
        __syncthreads();

        // ---- fold inv locally; write weights; attended (unnormalized + scale) ----
        float inv;
        {
            const float* redf = (const float*)(smb + RED_O);
            float sum = 0.f;
            #pragma unroll
            for (int w = 0; w < 16; ++w) sum += redf[w];
            inv = 1.0f / sum;
        }
        if (t < S_) {
            out[(size_t)B_ * E_ + (size_t)b * S_ + t] = scf[t] * inv;
        }
        {
            const int e2 = t & 63;          // float2 column (e = 2*e2, 2*e2+1)
            const int pp = t >> 6;          // 0..7
            const float2* kg = (const float2*)(keys + (size_t)b * (S_ * E_)) + e2;
            float a0 = 0.f, a1 = 0.f;
            const int sbeg = pp * 25;
            #pragma unroll
            for (int s = sbeg; s < sbeg + 25; ++s) {
                const float2 kv = kg[(size_t)s * 64];
                const float w = scf[s];
                a0 = fmaf(w, kv.x, a0);
                a1 = fmaf(w, kv.y, a1);
            }
            float2* apf = (float2*)(smb + AP_O);
            apf[pp * 64 + e2] = make_float2(a0, a1);
        }
        __syncthreads();
        if (t < E_) {
            const float* apf = (const float*)(smb + AP_O);
            float a = 0.f;
            #pragma unroll
            for (int g = 0; g < 8; ++g) a += apf[g * 128 + t];
            out[(size_t)b * E_ + t] = a * inv;
        }
        // next-iter loop-top __syncthreads orders AP/scf reuse
    }
}

extern "C" void kernel_launch(void* const* d_in, const int* in_sizes, int n_in,
                              void* d_out, int out_size) {
    const float* query = (const float*)d_in[0];
    const float* keys  = (const float*)d_in[1];
    const int*   mask  = (const int*)d_in[2];
    const float* W1    = (const float*)d_in[3];
    const float* b1    = (const float*)d_in[4];
    const float* W2    = (const float*)d_in[5];
    const float* b2    = (const float*)d_in[6];
    const float* W3    = (const float*)d_in[7];
    const float* b3    = (const float*)d_in[8];
    float* out = (float*)d_out;

    int nsm = 148;
    cudaDeviceGetAttribute(&nsm, cudaDevAttrMultiProcessorCount, 0);
    if (nsm < 112)  nsm = 112;
    if (nsm > 1024) nsm = 1024;

    cudaFuncSetAttribute(attn_persist_kernel,
                         cudaFuncAttributeMaxDynamicSharedMemorySize, SMEM_BYTES);
    attn_persist_kernel<<<nsm, 512, SMEM_BYTES>>>(query, keys, mask, W1, b1, W2, b2, W3, b3, out);
}

// round 15
// speedup vs baseline: 1.4140x; 1.1352x over previous
#include <cuda_runtime.h>
#include <cstdint>

#define B_ 4096
#define S_ 200
#define E_ 128
#define H_ 64
#define G_ 32

// ---- SMEM layout (bytes) --------------------------------------------------
#define KEYS_O   0          // 200 rows x 512B: fp32 staged -> in-place hi|lo bf16, xor-swizzled
#define W1T_O    102400     // 64 rows x 512B (hi|lo), resident
#define W2T_O    135168     // 32 rows x 256B (hi|lo), resident
#define QWALL_O  143360     // up to 37 iters x 64 f
#define SC0_O    153600     // score slot 0 (200 f)
#define SC1_O    154400     // score slot 1 (200 f)
#define SCR_O    155200     // consumer scratch (8 f)
#define AP_O     155264     // 3 x 128 f attended partials
#define W3S_O    156800     // 32 f
#define B2S_O    156928     // 32 f
#define B3S_O    157056     // 1 f
#define SMEM_BYTES 157184

// prologue staging (inside KEYS region)
#define PW1_O    0
#define PW2_O    65536
#define PQ_O     73728
#define PB1_O    94208

static __device__ __forceinline__ uint32_t cvta_smem(const void* p) {
    uint32_t a;
    asm("{ .reg .u64 t; cvta.to.shared.u64 t, %1; cvt.u32.u64 %0, t; }" : "=r"(a) : "l"(p));
    return a;
}
static __device__ __forceinline__ uint32_t pk(float lo, float hi) {
    uint32_t r;
    asm("cvt.rn.bf16x2.f32 %0, %1, %2;" : "=r"(r) : "f"(hi), "f"(lo));
    return r;
}
static __device__ __forceinline__ float blo(uint32_t u) { return __uint_as_float(u << 16); }
static __device__ __forceinline__ float bhi(uint32_t u) { return __uint_as_float(u & 0xffff0000u); }

static __device__ __forceinline__ void ldsm4(uint32_t& r0, uint32_t& r1, uint32_t& r2, uint32_t& r3,
                                             uint32_t addr) {
    asm volatile("ldmatrix.sync.aligned.m8n8.x4.shared.b16 {%0,%1,%2,%3}, [%4];"
                 : "=r"(r0), "=r"(r1), "=r"(r2), "=r"(r3) : "r"(addr));
}
static __device__ __forceinline__ uint32_t lds32(uint32_t addr) {
    uint32_t v;
    asm volatile("ld.shared.u32 %0, [%1];" : "=r"(v) : "r"(addr));
    return v;
}
static __device__ __forceinline__ void mma_bf16(float* c, const uint32_t* a, uint32_t b0, uint32_t b1) {
    asm volatile("mma.sync.aligned.m16n8k16.row.col.f32.bf16.bf16.f32 "
                 "{%0,%1,%2,%3}, {%4,%5,%6,%7}, {%8,%9}, {%0,%1,%2,%3};"
                 : "+f"(c[0]), "+f"(c[1]), "+f"(c[2]), "+f"(c[3])
                 : "r"(a[0]), "r"(a[1]), "r"(a[2]), "r"(a[3]), "r"(b0), "r"(b1));
}

#define CPA(sm, g) asm volatile("cp.async.cg.shared.global [%0], [%1], 16;" :: "r"(sm), "l"(g))
#define CPC()      asm volatile("cp.async.commit_group;" ::: "memory")
#define CPW(n)     asm volatile("cp.async.wait_group %0;" :: "n"(n) : "memory")

// named barriers: 1,2 = scores-ready (parity), 3,4 = slot-free (parity), 7 = consumer-local
#define BSYNC(id)   asm volatile("bar.sync %0, 512;"   :: "r"(id) : "memory")
#define BARRIVE(id) asm volatile("bar.arrive %0, 512;" :: "r"(id) : "memory")
#define MEMBAR()    asm volatile("membar.cta;" ::: "memory")
#define CBAR()      asm volatile("bar.sync 7, 96;" ::: "memory")

// convert one key row r: fp32 (512B) -> hi/lo bf16, in place, swizzled
#define CONV_ROW(r) do { \
    const uint32_t rowb = (uint32_t)((r) * 512); \
    const float4 v = *(const float4*)(smb + rowb + lane * 16); \
    const uint32_t h01 = pk(v.x, v.y), h23 = pk(v.z, v.w); \
    const uint32_t l01 = pk(v.x - blo(h01), v.y - bhi(h01)); \
    const uint32_t l23 = pk(v.z - blo(h23), v.w - bhi(h23)); \
    const uint32_t xo = (uint32_t)(((r) & 7) << 4); \
    *(uint64_t*)(smb + rowb + ((lane * 8) ^ xo))       = (uint64_t)h01 | ((uint64_t)h23 << 32); \
    *(uint64_t*)(smb + rowb + 256 + ((lane * 8) ^ xo)) = (uint64_t)l01 | ((uint64_t)l23 << 32); \
} while (0)

__global__ __launch_bounds__(512, 1)
void attn_persist_kernel(const float* __restrict__ query,
                         const float* __restrict__ keys,
                         const int*   __restrict__ mask,
                         const float* __restrict__ W1,
                         const float* __restrict__ b1,
                         const float* __restrict__ W2,
                         const float* __restrict__ b2,
                         const float* __restrict__ W3,
                         const float* __restrict__ b3,
                         float* __restrict__ out)
{
    extern __shared__ char smb[];
    const uint32_t sb = cvta_smem(smb);
    const int t    = threadIdx.x;
    const int warp = t >> 5;
    const int lane = t & 31;
    const int grid = gridDim.x;
    const int nb   = (B_ - blockIdx.x + grid - 1) / grid;

    // ================= Prologue (all 512 threads) =================
    {
        #pragma unroll 4
        for (int i = t; i < 4096; i += 512) CPA(sb + PW1_O + i * 16, (const char*)W1 + i * 16);
        CPA(sb + PW2_O + t * 16, (const char*)W2 + t * 16);
        for (int j = t; j < nb * 32; j += 512) {
            const int bi = blockIdx.x + (j >> 5) * grid;
            CPA(sb + PQ_O + j * 16, (const char*)(query + (size_t)bi * E_) + (j & 31) * 16);
        }
        if (t < 16) CPA(sb + PB1_O + t * 16, (const char*)b1 + t * 16);
        if (t < 8)  CPA(sb + W3S_O + t * 16, (const char*)W3 + t * 16);
        if (t < 8)  CPA(sb + B2S_O + t * 16, (const char*)b2 + t * 16);
        CPC();
    }
    CPW(0);
    if (t == 0) ((float*)(smb + B3S_O))[0] = b3[0];
    __syncthreads();

    // W1T (rows 128..255 of W1) hi/lo bf16, swizzled
    {
        const float* stg = (const float*)(smb + PW1_O + 32768);
        #pragma unroll
        for (int p = t; p < 4096; p += 512) {
            const int n  = p & 63;
            const int kp = p >> 6;
            const float a = stg[(2 * kp) * H_ + n];
            const float c = stg[(2 * kp + 1) * H_ + n];
            const uint32_t hu = pk(a, c);
            const uint32_t lu = pk(a - blo(hu), c - bhi(hu));
            char* dst = smb + W1T_O + n * 512 + (((uint32_t)(kp * 4)) ^ ((n & 7) << 4));
            *(uint32_t*)dst = hu;
            *(uint32_t*)(dst + 256) = lu;
        }
    }
    // W2T hi/lo bf16, swizzled
    {
        const float* stg2 = (const float*)(smb + PW2_O);
        #pragma unroll
        for (int p = t; p < 1024; p += 512) {
            const int g  = p & 31;
            const int hp = p >> 5;
            const float a = stg2[(2 * hp) * G_ + g];
            const float c = stg2[(2 * hp + 1) * G_ + g];
            const uint32_t hu = pk(a, c);
            const uint32_t lu = pk(a - blo(hu), c - bhi(hu));
            char* dst = smb + W2T_O + g * 256 + (((uint32_t)(hp * 4)) ^ ((g & 7) << 4));
            *(uint32_t*)dst = hu;
            *(uint32_t*)(dst + 128) = lu;
        }
    }
    // qw[i][h] for all assigned b's
    {
        const float* w1top = (const float*)(smb + PW1_O);
        const float* b1f   = (const float*)(smb + PB1_O);
        const int h    = t & 63;
        const int isub = t >> 6;
        for (int i0 = 0; i0 < nb; i0 += 8) {
            const int i = i0 + isub;
            if (i < nb) {
                const float* q = (const float*)(smb + PQ_O) + i * 128;
                float s = b1f[h];
                #pragma unroll 8
                for (int e = 0; e < 128; ++e) s = fmaf(q[e], w1top[e * 64 + h], s);
                ((float*)(smb + QWALL_O))[i * 64 + h] = s;
            }
        }
    }
    __syncthreads();

    // producers: fetch own rows of first keys tile (warp-local, visibility via own CPW)
    if (warp < 13) {
        const int m0 = warp * 16;
        const int nrows = (m0 + 16 <= S_) ? 16 : (S_ - m0);
        const char* gk = (const char*)keys + ((size_t)blockIdx.x * (S_ * E_) + (size_t)m0 * E_) * 4;
        #pragma unroll 4
        for (int c = lane; c < nrows * 32; c += 32)
            CPA(sb + KEYS_O + m0 * 512 + c * 16, gk + (size_t)c * 16);
        CPC();
    }
    // NOTE: no barrier priming. Producers skip BSYNC(slot) for it<2, which IS
    // the priming; an extra consumer arrival here would misalign barrier
    // generations (512-trip fires mid-producer-group -> deadlock; R14 bug).

    const int r0 = lane >> 2;
    const int cb = (lane & 3) * 2;

    // ================= Main loop =================
    for (int it = 0; it < nb; ++it) {
        const int b = blockIdx.x + it * grid;
        float* scf = (float*)(smb + ((it & 1) ? SC1_O : SC0_O));

        if (warp < 13) {
            // ======== PRODUCER: warps 0-12 ========
            CPW(0);              // own keys prefetch landed
            const int m0 = warp * 16;

            // mask for this warp's two rows via LDG (consumed much later)
            int mA = 1, mB = 1;
            {
                const int rowA_ = m0 + r0, rowB_ = rowA_ + 8;
                const int* gm = mask + (size_t)b * S_;
                if ((lane & 3) == 0) {
                    if (rowA_ < S_) mA = gm[rowA_];
                    if (rowB_ < S_) mB = gm[rowB_];
                }
            }

            // ---- warp-local convert ----
            if (m0 + 16 <= S_) {
                #pragma unroll
                for (int i = 0; i < 16; ++i) CONV_ROW(m0 + i);
            } else {
                #pragma unroll
                for (int i = 0; i < 8; ++i) CONV_ROW(m0 + i);   // warp 12: rows 192-199
            }
            __syncwarp();

            // ---- Layer 1 ----
            float acc[8][4];
            #pragma unroll
            for (int n = 0; n < 8; ++n)
                #pragma unroll
                for (int j = 0; j < 4; ++j) acc[n][j] = 0.f;

            const uint32_t axor   = (uint32_t)((lane & 7) << 4);
            const uint32_t a_base = sb + KEYS_O + (m0 + (lane & 15)) * 512;
            const uint32_t ag16   = (uint32_t)((lane >> 4) << 4);
            const uint32_t bxor   = (uint32_t)((lane >> 2) << 4);
            const uint32_t bl4    = (uint32_t)((lane & 3) * 4);
            const uint32_t brow0  = sb + W1T_O + (lane >> 2) * 512;

            #pragma unroll
            for (int k = 0; k < 8; ++k) {
                uint32_t ah[4], al[4];
                const uint32_t ac = ((uint32_t)(k * 32) + ag16) ^ axor;
                ldsm4(ah[0], ah[1], ah[2], ah[3], a_base + ac);
                ldsm4(al[0], al[1], al[2], al[3], a_base + 256 + ac);
                const uint32_t c0 = ((uint32_t)(k * 32) ^ bxor) + bl4;
                const uint32_t c1 = ((uint32_t)(k * 32 + 16) ^ bxor) + bl4;
                #pragma unroll
                for (int n = 0; n < 8; ++n) {
                    const uint32_t brow = brow0 + n * (8 * 512);
                    const uint32_t bh0 = lds32(brow + c0);
                    const uint32_t bh1 = lds32(brow + c1);
                    const uint32_t bl0 = lds32(brow + 256 + c0);
                    const uint32_t bl1 = lds32(brow + 256 + c1);
                    mma_bf16(acc[n], ah, bh0, bh1);
                    mma_bf16(acc[n], ah, bl0, bl1);
                    mma_bf16(acc[n], al, bh0, bh1);
                }
            }

            // ---- early warp-local prefetch of next b's own key rows ----
            if (it + 1 < nb) {
                const int bn = b + grid;
                const int nrows = (m0 + 16 <= S_) ? 16 : (S_ - m0);
                const char* gk = (const char*)keys +
                                 ((size_t)bn * (S_ * E_) + (size_t)m0 * E_) * 4;
                #pragma unroll 4
                for (int c = lane; c < nrows * 32; c += 32)
                    CPA(sb + KEYS_O + m0 * 512 + c * 16, gk + (size_t)c * 16);
                CPC();
            }

            // ---- epilogue -> A-fragments ----
            uint32_t ahf[4][4], alf[4][4];
            const float* qwf = (const float*)(smb + QWALL_O) + it * 64;
            #pragma unroll
            for (int kt = 0; kt < 4; ++kt) {
                #pragma unroll
                for (int half = 0; half < 2; ++half) {
                    const int n = 2 * kt + half;
                    const int c = n * 8 + cb;
                    const float qa = qwf[c], qb = qwf[c + 1];
                    const float v0 = fmaxf(acc[n][0] + qa, 0.f);
                    const float v1 = fmaxf(acc[n][1] + qb, 0.f);
                    const float v2 = fmaxf(acc[n][2] + qa, 0.f);
                    const float v3 = fmaxf(acc[n][3] + qb, 0.f);
                    const uint32_t h01 = pk(v0, v1), h23 = pk(v2, v3);
                    ahf[kt][2 * half]     = h01;
                    ahf[kt][2 * half + 1] = h23;
                    alf[kt][2 * half]     = pk(v0 - blo(h01), v1 - bhi(h01));
                    alf[kt][2 * half + 1] = pk(v2 - blo(h23), v3 - bhi(h23));
                }
            }

            // ---- Layer 2 ----
            float acc2[4][4];
            #pragma unroll
            for (int n = 0; n < 4; ++n)
                #pragma unroll
                for (int j = 0; j < 4; ++j) acc2[n][j] = 0.f;

            const uint32_t b2row0 = sb + W2T_O + (lane >> 2) * 256;
            #pragma unroll
            for (int kt = 0; kt < 4; ++kt) {
                const uint32_t c0 = ((uint32_t)(kt * 32) ^ bxor) + bl4;
                const uint32_t c1 = ((uint32_t)(kt * 32 + 16) ^ bxor) + bl4;
                #pragma unroll
                for (int n = 0; n < 4; ++n) {
                    const uint32_t brow = b2row0 + n * (8 * 256);
                    const uint32_t bh0 = lds32(brow + c0);
                    const uint32_t bh1 = lds32(brow + c1);
                    const uint32_t bl0 = lds32(brow + 128 + c0);
                    const uint32_t bl1 = lds32(brow + 128 + c1);
                    mma_bf16(acc2[n], ahf[kt], bh0, bh1);
                    mma_bf16(acc2[n], ahf[kt], bl0, bl1);
                    mma_bf16(acc2[n], alf[kt], bh0, bh1);
                }
            }

            // ---- Layer 3 ----
            const float* b2f = (const float*)(smb + B2S_O);
            const float* w3f = (const float*)(smb + W3S_O);
            float p0 = 0.f, p8 = 0.f;
            #pragma unroll
            for (int n = 0; n < 4; ++n) {
                const int c = n * 8 + cb;
                const float w3a = w3f[c], w3b = w3f[c + 1];
                const float ba = b2f[c],  bb = b2f[c + 1];
                p0 = fmaf(fmaxf(acc2[n][0] + ba, 0.f), w3a,
                     fmaf(fmaxf(acc2[n][1] + bb, 0.f), w3b, p0));
                p8 = fmaf(fmaxf(acc2[n][2] + ba, 0.f), w3a,
                     fmaf(fmaxf(acc2[n][3] + bb, 0.f), w3b, p8));
            }
            p0 += __shfl_xor_sync(0xffffffffu, p0, 1);
            p0 += __shfl_xor_sync(0xffffffffu, p0, 2);
            p8 += __shfl_xor_sync(0xffffffffu, p8, 1);
            p8 += __shfl_xor_sync(0xffffffffu, p8, 2);

            // wait until consumers freed this score slot (generation pairs with
            // consumer arrivals from iter it-2; first two iters need no wait)
            if (it >= 2) BSYNC(3 + (it & 1));

            if ((lane & 3) == 0) {
                const int rowA = m0 + r0;
                const int rowB = rowA + 8;
                const float b3v = ((const float*)(smb + B3S_O))[0];
                if (rowA < S_) {
                    float sc = p0 + b3v;
                    if (mA == 0) sc = -1e9f;
                    scf[rowA] = sc;
                }
                if (rowB < S_) {
                    float sc = p8 + b3v;
                    if (mB == 0) sc = -1e9f;
                    scf[rowB] = sc;
                }
            }
            MEMBAR();                 // publish score writes before arrive
            BARRIVE(1 + (it & 1));    // scores(it) ready

        } else {
            // ======== CONSUMER: warps 13-15 (96 threads) ========
            const int tc = t - 416;           // 0..95
            const int cwarp = tc >> 5;        // 0..2
            float* scr = (float*)(smb + SCR_O);

            BSYNC(1 + (it & 1));              // wait scores(it)

            // max
            float v0 = scf[tc];
            float v1 = scf[tc + 96];
            float v2 = (tc < 8) ? scf[tc + 192] : -3e38f;
            float mx = fmaxf(fmaxf(v0, v1), v2);
            #pragma unroll
            for (int o = 16; o; o >>= 1) mx = fmaxf(mx, __shfl_xor_sync(0xffffffffu, mx, o));
            if ((tc & 31) == 0) scr[cwarp] = mx;
            CBAR();
            mx = fmaxf(scr[0], fmaxf(scr[1], scr[2]));

            // exp + sum (scf becomes unnormalized exp)
            const float e0 = __expf(v0 - mx);
            const float e1 = __expf(v1 - mx);
            const float e2 = (tc < 8) ? __expf(v2 - mx) : 0.f;
            scf[tc] = e0;
            scf[tc + 96] = e1;
            if (tc < 8) scf[tc + 192] = e2;
            float ps = e0 + e1 + e2;
            #pragma unroll
            for (int o = 16; o; o >>= 1) ps += __shfl_xor_sync(0xffffffffu, ps, o);
            if ((tc & 31) == 0) scr[3 + cwarp] = ps;
            CBAR();                            // also publishes all exp writes
            const float inv = 1.0f / (scr[3] + scr[4] + scr[5]);

            // weights out
            {
                float* out_w = out + (size_t)B_ * E_ + (size_t)b * S_;
                out_w[tc] = e0 * inv;
                out_w[tc + 96] = e1 * inv;
                if (tc < 8) out_w[tc + 192] = e2 * inv;
            }

            // attended: 3 partitions x ~67 s, float4 keys (L2-hot)
            {
                const int col = tc & 31;      // float4 column
                const float4* kg = (const float4*)(keys + (size_t)b * (S_ * E_)) + col;
                float a0 = 0.f, a1 = 0.f, a2 = 0.f, a3 = 0.f;
                const int sbeg = cwarp * 67;
                const int send = (cwarp == 2) ? S_ : sbeg + 67;
                #pragma unroll 4
                for (int s = sbeg; s < send; ++s) {
                    const float4 kv = kg[(size_t)s * 32];
                    const float w = scf[s];
                    a0 = fmaf(w, kv.x, a0);
                    a1 = fmaf(w, kv.y, a1);
                    a2 = fmaf(w, kv.z, a2);
                    a3 = fmaf(w, kv.w, a3);
                }
                ((float4*)(smb + AP_O))[cwarp * 32 + col] = make_float4(a0, a1, a2, a3);
            }
            CBAR();
            {
                const float* apf = (const float*)(smb + AP_O);
                float* ob = out + (size_t)b * E_;
                {
                    const int e = tc;
                    ob[e] = (apf[e] + apf[128 + e] + apf[256 + e]) * inv;
                }
                if (tc < 32) {
                    const int e = tc + 96;
                    ob[e] = (apf[e] + apf[128 + e] + apf[256 + e]) * inv;
                }
            }
            MEMBAR();                         // order scf reads/AP writes before release
            BARRIVE(3 + (it & 1));            // slot(it) free
        }
    }
}

extern "C" void kernel_launch(void* const* d_in, const int* in_sizes, int n_in,
                              void* d_out, int out_size) {
    const float* query = (const float*)d_in[0];
    const float* keys  = (const float*)d_in[1];
    const int*   mask  = (const int*)d_in[2];
    const float* W1    = (const float*)d_in[3];
    const float* b1    = (const float*)d_in[4];
    const float* W2    = (const float*)d_in[5];
    const float* b2    = (const float*)d_in[6];
    const float* W3    = (const float*)d_in[7];
    const float* b3    = (const float*)d_in[8];
    float* out = (float*)d_out;

    int nsm = 148;
    cudaDeviceGetAttribute(&nsm, cudaDevAttrMultiProcessorCount, 0);
    if (nsm < 112)  nsm = 112;
    if (nsm > 1024) nsm = 1024;

    cudaFuncSetAttribute(attn_persist_kernel,
                         cudaFuncAttributeMaxDynamicSharedMemorySize, SMEM_BYTES);
    attn_persist_kernel<<<nsm, 512, SMEM_BYTES>>>(query, keys, mask, W1, b1, W2, b2, W3, b3, out);
}

// round 16
// speedup vs baseline: 1.5078x; 1.0664x over previous
#include <cuda_runtime.h>
#include <cstdint>

#define B_ 4096
#define S_ 200
#define E_ 128
#define H_ 64
#define G_ 32

// ---- SMEM layout (bytes) --------------------------------------------------
#define KEYS_O   0          // 200 rows x 512B: fp32 staged -> in-place hi|lo bf16, xor-swizzled
#define W1T_O    102400     // 64 rows x 512B (hi|lo), resident
#define W2T_O    135168     // 32 rows x 256B (hi|lo), resident
#define QWALL_O  143360     // up to 37 iters x 64 f
#define SC0_O    153600     // score slot 0 (200 f)
#define SC1_O    154400     // score slot 1 (200 f)
#define SCR_O    155200     // consumer scratch (8 f)
#define AP_O     155264     // 3 x 128 f attended partials
#define W3S_O    156800     // 32 f
#define B2S_O    156928     // 32 f
#define B3S_O    157056     // 1 f
#define SMEM_BYTES 157184

// prologue staging (inside KEYS region)
#define PW1_O    0
#define PW2_O    65536
#define PQ_O     73728
#define PB1_O    94208

static __device__ __forceinline__ uint32_t cvta_smem(const void* p) {
    uint32_t a;
    asm("{ .reg .u64 t; cvta.to.shared.u64 t, %1; cvt.u32.u64 %0, t; }" : "=r"(a) : "l"(p));
    return a;
}
static __device__ __forceinline__ uint32_t pk(float lo, float hi) {
    uint32_t r;
    asm("cvt.rn.bf16x2.f32 %0, %1, %2;" : "=r"(r) : "f"(hi), "f"(lo));
    return r;
}
static __device__ __forceinline__ float blo(uint32_t u) { return __uint_as_float(u << 16); }
static __device__ __forceinline__ float bhi(uint32_t u) { return __uint_as_float(u & 0xffff0000u); }

static __device__ __forceinline__ void ldsm4(uint32_t& r0, uint32_t& r1, uint32_t& r2, uint32_t& r3,
                                             uint32_t addr) {
    asm volatile("ldmatrix.sync.aligned.m8n8.x4.shared.b16 {%0,%1,%2,%3}, [%4];"
                 : "=r"(r0), "=r"(r1), "=r"(r2), "=r"(r3) : "r"(addr));
}
static __device__ __forceinline__ void mma_bf16(float* c, const uint32_t* a, uint32_t b0, uint32_t b1) {
    asm volatile("mma.sync.aligned.m16n8k16.row.col.f32.bf16.bf16.f32 "
                 "{%0,%1,%2,%3}, {%4,%5,%6,%7}, {%8,%9}, {%0,%1,%2,%3};"
                 : "+f"(c[0]), "+f"(c[1]), "+f"(c[2]), "+f"(c[3])
                 : "r"(a[0]), "r"(a[1]), "r"(a[2]), "r"(a[3]), "r"(b0), "r"(b1));
}

#define CPA(sm, g) asm volatile("cp.async.cg.shared.global [%0], [%1], 16;" :: "r"(sm), "l"(g))
#define CPC()      asm volatile("cp.async.commit_group;" ::: "memory")
#define CPW(n)     asm volatile("cp.async.wait_group %0;" :: "n"(n) : "memory")

// named barriers: 1,2 = scores-ready (parity), 3,4 = slot-free (parity), 7 = consumer-local
#define BSYNC(id)   asm volatile("bar.sync %0, 512;"   :: "r"(id) : "memory")
#define BARRIVE(id) asm volatile("bar.arrive %0, 512;" :: "r"(id) : "memory")
#define MEMBAR()    asm volatile("membar.cta;" ::: "memory")
#define CBAR()      asm volatile("bar.sync 7, 96;" ::: "memory")

// convert one key row r: fp32 (512B) -> hi/lo bf16, in place, swizzled
#define CONV_ROW(r) do { \
    const uint32_t rowb = (uint32_t)((r) * 512); \
    const float4 v = *(const float4*)(smb + rowb + lane * 16); \
    const uint32_t h01 = pk(v.x, v.y), h23 = pk(v.z, v.w); \
    const uint32_t l01 = pk(v.x - blo(h01), v.y - bhi(h01)); \
    const uint32_t l23 = pk(v.z - blo(h23), v.w - bhi(h23)); \
    const uint32_t xo = (uint32_t)(((r) & 7) << 4); \
    *(uint64_t*)(smb + rowb + ((lane * 8) ^ xo))       = (uint64_t)h01 | ((uint64_t)h23 << 32); \
    *(uint64_t*)(smb + rowb + 256 + ((lane * 8) ^ xo)) = (uint64_t)l01 | ((uint64_t)l23 << 32); \
} while (0)

__global__ __launch_bounds__(512, 1)
void attn_persist_kernel(const float* __restrict__ query,
                         const float* __restrict__ keys,
                         const int*   __restrict__ mask,
                         const float* __restrict__ W1,
                         const float* __restrict__ b1,
                         const float* __restrict__ W2,
                         const float* __restrict__ b2,
                         const float* __restrict__ W3,
                         const float* __restrict__ b3,
                         float* __restrict__ out)
{
    extern __shared__ char smb[];
    const uint32_t sb = cvta_smem(smb);
    const int t    = threadIdx.x;
    const int warp = t >> 5;
    const int lane = t & 31;
    const int grid = gridDim.x;
    const int nb   = (B_ - blockIdx.x + grid - 1) / grid;

    // ================= Prologue (all 512 threads) =================
    {
        #pragma unroll 4
        for (int i = t; i < 4096; i += 512) CPA(sb + PW1_O + i * 16, (const char*)W1 + i * 16);
        CPA(sb + PW2_O + t * 16, (const char*)W2 + t * 16);
        for (int j = t; j < nb * 32; j += 512) {
            const int bi = blockIdx.x + (j >> 5) * grid;
            CPA(sb + PQ_O + j * 16, (const char*)(query + (size_t)bi * E_) + (j & 31) * 16);
        }
        if (t < 16) CPA(sb + PB1_O + t * 16, (const char*)b1 + t * 16);
        if (t < 8)  CPA(sb + W3S_O + t * 16, (const char*)W3 + t * 16);
        if (t < 8)  CPA(sb + B2S_O + t * 16, (const char*)b2 + t * 16);
        CPC();
    }
    CPW(0);
    if (t == 0) ((float*)(smb + B3S_O))[0] = b3[0];
    __syncthreads();

    // W1T (rows 128..255 of W1) hi/lo bf16, swizzled
    {
        const float* stg = (const float*)(smb + PW1_O + 32768);
        #pragma unroll
        for (int p = t; p < 4096; p += 512) {
            const int n  = p & 63;
            const int kp = p >> 6;
            const float a = stg[(2 * kp) * H_ + n];
            const float c = stg[(2 * kp + 1) * H_ + n];
            const uint32_t hu = pk(a, c);
            const uint32_t lu = pk(a - blo(hu), c - bhi(hu));
            char* dst = smb + W1T_O + n * 512 + (((uint32_t)(kp * 4)) ^ ((n & 7) << 4));
            *(uint32_t*)dst = hu;
            *(uint32_t*)(dst + 256) = lu;
        }
    }
    // W2T hi/lo bf16, swizzled
    {
        const float* stg2 = (const float*)(smb + PW2_O);
        #pragma unroll
        for (int p = t; p < 1024; p += 512) {
            const int g  = p & 31;
            const int hp = p >> 5;
            const float a = stg2[(2 * hp) * G_ + g];
            const float c = stg2[(2 * hp + 1) * G_ + g];
            const uint32_t hu = pk(a, c);
            const uint32_t lu = pk(a - blo(hu), c - bhi(hu));
            char* dst = smb + W2T_O + g * 256 + (((uint32_t)(hp * 4)) ^ ((g & 7) << 4));
            *(uint32_t*)dst = hu;
            *(uint32_t*)(dst + 128) = lu;
        }
    }
    // qw[i][h] for all assigned b's
    {
        const float* w1top = (const float*)(smb + PW1_O);
        const float* b1f   = (const float*)(smb + PB1_O);
        const int h    = t & 63;
        const int isub = t >> 6;
        for (int i0 = 0; i0 < nb; i0 += 8) {
            const int i = i0 + isub;
            if (i < nb) {
                const float* q = (const float*)(smb + PQ_O) + i * 128;
                float s = b1f[h];
                #pragma unroll 8
                for (int e = 0; e < 128; ++e) s = fmaf(q[e], w1top[e * 64 + h], s);
                ((float*)(smb + QWALL_O))[i * 64 + h] = s;
            }
        }
    }
    __syncthreads();

    // producers: fetch own rows of first keys tile (warp-local, visibility via own CPW)
    if (warp < 13) {
        const int m0 = warp * 16;
        const int nrows = (m0 + 16 <= S_) ? 16 : (S_ - m0);
        const char* gk = (const char*)keys + ((size_t)blockIdx.x * (S_ * E_) + (size_t)m0 * E_) * 4;
        #pragma unroll 4
        for (int c = lane; c < nrows * 32; c += 32)
            CPA(sb + KEYS_O + m0 * 512 + c * 16, gk + (size_t)c * 16);
        CPC();
    }
    // NOTE: no barrier priming (producers skipping BSYNC(slot) for it<2 IS the priming).

    const int r0 = lane >> 2;
    const int cb = (lane & 3) * 2;

    // B-operand ldmatrix addressing (shared by layer 1 and 2):
    // lane group g = lane>>3: tiles {rows +0,k+0},{+0,k+16B},{+8,k+0},{+8,k+16B}
    const int      brow  = (lane & 7) + ((lane >> 4) << 3);
    const uint32_t bkoff = (uint32_t)(((lane >> 3) & 1) << 4);
    const uint32_t bxv   = (uint32_t)((lane & 7) << 4);
    const uint32_t bsel  = bkoff ^ (bxv & 0x10);   // carry-free split of (k*32+koff)^xorv
    const uint32_t bxhi  = bxv & 0x60;

    // ================= Main loop =================
    for (int it = 0; it < nb; ++it) {
        const int b = blockIdx.x + it * grid;
        float* scf = (float*)(smb + ((it & 1) ? SC1_O : SC0_O));

        if (warp < 13) {
            // ======== PRODUCER: warps 0-12 ========
            CPW(0);              // own keys prefetch landed
            const int m0 = warp * 16;

            // mask for this warp's two rows via LDG (consumed much later)
            int mA = 1, mB = 1;
            {
                const int rowA_ = m0 + r0, rowB_ = rowA_ + 8;
                const int* gm = mask + (size_t)b * S_;
                if ((lane & 3) == 0) {
                    if (rowA_ < S_) mA = gm[rowA_];
                    if (rowB_ < S_) mB = gm[rowB_];
                }
            }

            // ---- warp-local convert ----
            if (m0 + 16 <= S_) {
                #pragma unroll
                for (int i = 0; i < 16; ++i) CONV_ROW(m0 + i);
            } else {
                #pragma unroll
                for (int i = 0; i < 8; ++i) CONV_ROW(m0 + i);   // warp 12: rows 192-199
            }
            __syncwarp();

            // ---- Layer 1 (B via ldmatrix.x4) ----
            float acc[8][4];
            #pragma unroll
            for (int n = 0; n < 8; ++n)
                #pragma unroll
                for (int j = 0; j < 4; ++j) acc[n][j] = 0.f;

            const uint32_t axor   = (uint32_t)((lane & 7) << 4);
            const uint32_t a_base = sb + KEYS_O + (m0 + (lane & 15)) * 512;
            const uint32_t ag16   = (uint32_t)((lane >> 4) << 4);
            const uint32_t bbase1 = sb + W1T_O + brow * 512 + bsel;

            #pragma unroll
            for (int k = 0; k < 8; ++k) {
                uint32_t ah[4], al[4];
                const uint32_t ac = ((uint32_t)(k * 32) + ag16) ^ axor;
                ldsm4(ah[0], ah[1], ah[2], ah[3], a_base + ac);
                ldsm4(al[0], al[1], al[2], al[3], a_base + 256 + ac);
                const uint32_t kc = ((uint32_t)(k * 32)) ^ bxhi;
                #pragma unroll
                for (int j = 0; j < 4; ++j) {
                    uint32_t bh[4], bl[4];
                    const uint32_t ba = bbase1 + (uint32_t)(j * 8192) + kc;
                    ldsm4(bh[0], bh[1], bh[2], bh[3], ba);
                    ldsm4(bl[0], bl[1], bl[2], bl[3], ba + 256);
                    mma_bf16(acc[2 * j],     ah, bh[0], bh[1]);
                    mma_bf16(acc[2 * j],     ah, bl[0], bl[1]);
                    mma_bf16(acc[2 * j],     al, bh[0], bh[1]);
                    mma_bf16(acc[2 * j + 1], ah, bh[2], bh[3]);
                    mma_bf16(acc[2 * j + 1], ah, bl[2], bl[3]);
                    mma_bf16(acc[2 * j + 1], al, bh[2], bh[3]);
                }
            }

            // ---- early warp-local prefetch of next b's own key rows ----
            if (it + 1 < nb) {
                const int bn = b + grid;
                const int nrows = (m0 + 16 <= S_) ? 16 : (S_ - m0);
                const char* gk = (const char*)keys +
                                 ((size_t)bn * (S_ * E_) + (size_t)m0 * E_) * 4;
                #pragma unroll 4
                for (int c = lane; c < nrows * 32; c += 32)
                    CPA(sb + KEYS_O + m0 * 512 + c * 16, gk + (size_t)c * 16);
                CPC();
            }

            // ---- epilogue -> A-fragments ----
            uint32_t ahf[4][4], alf[4][4];
            const float* qwf = (const float*)(smb + QWALL_O) + it * 64;
            #pragma unroll
            for (int kt = 0; kt < 4; ++kt) {
                #pragma unroll
                for (int half = 0; half < 2; ++half) {
                    const int n = 2 * kt + half;
                    const int c = n * 8 + cb;
                    const float qa = qwf[c], qb = qwf[c + 1];
                    const float v0 = fmaxf(acc[n][0] + qa, 0.f);
                    const float v1 = fmaxf(acc[n][1] + qb, 0.f);
                    const float v2 = fmaxf(acc[n][2] + qa, 0.f);
                    const float v3 = fmaxf(acc[n][3] + qb, 0.f);
                    const uint32_t h01 = pk(v0, v1), h23 = pk(v2, v3);
                    ahf[kt][2 * half]     = h01;
                    ahf[kt][2 * half + 1] = h23;
                    alf[kt][2 * half]     = pk(v0 - blo(h01), v1 - bhi(h01));
                    alf[kt][2 * half + 1] = pk(v2 - blo(h23), v3 - bhi(h23));
                }
            }

            // ---- Layer 2 (B via ldmatrix.x4) ----
            float acc2[4][4];
            #pragma unroll
            for (int n = 0; n < 4; ++n)
                #pragma unroll
                for (int j = 0; j < 4; ++j) acc2[n][j] = 0.f;

            const uint32_t bbase2 = sb + W2T_O + brow * 256 + bsel;
            #pragma unroll
            for (int kt = 0; kt < 4; ++kt) {
                const uint32_t kc = ((uint32_t)(kt * 32)) ^ bxhi;
                #pragma unroll
                for (int j = 0; j < 2; ++j) {
                    uint32_t bh[4], bl[4];
                    const uint32_t ba = bbase2 + (uint32_t)(j * 4096) + kc;
                    ldsm4(bh[0], bh[1], bh[2], bh[3], ba);
                    ldsm4(bl[0], bl[1], bl[2], bl[3], ba + 128);
                    mma_bf16(acc2[2 * j],     ahf[kt], bh[0], bh[1]);
                    mma_bf16(acc2[2 * j],     ahf[kt], bl[0], bl[1]);
                    mma_bf16(acc2[2 * j],     alf[kt], bh[0], bh[1]);
                    mma_bf16(acc2[2 * j + 1], ahf[kt], bh[2], bh[3]);
                    mma_bf16(acc2[2 * j + 1], ahf[kt], bl[2], bl[3]);
                    mma_bf16(acc2[2 * j + 1], alf[kt], bh[2], bh[3]);
                }
            }

            // ---- Layer 3 ----
            const float* b2f = (const float*)(smb + B2S_O);
            const float* w3f = (const float*)(smb + W3S_O);
            float p0 = 0.f, p8 = 0.f;
            #pragma unroll
            for (int n = 0; n < 4; ++n) {
                const int c = n * 8 + cb;
                const float w3a = w3f[c], w3b = w3f[c + 1];
                const float ba = b2f[c],  bb = b2f[c + 1];
                p0 = fmaf(fmaxf(acc2[n][0] + ba, 0.f), w3a,
                     fmaf(fmaxf(acc2[n][1] + bb, 0.f), w3b, p0));
                p8 = fmaf(fmaxf(acc2[n][2] + ba, 0.f), w3a,
                     fmaf(fmaxf(acc2[n][3] + bb, 0.f), w3b, p8));
            }
            p0 += __shfl_xor_sync(0xffffffffu, p0, 1);
            p0 += __shfl_xor_sync(0xffffffffu, p0, 2);
            p8 += __shfl_xor_sync(0xffffffffu, p8, 1);
            p8 += __shfl_xor_sync(0xffffffffu, p8, 2);

            // wait until consumers freed this score slot (iter it-2)
            if (it >= 2) BSYNC(3 + (it & 1));

            if ((lane & 3) == 0) {
                const int rowA = m0 + r0;
                const int rowB = rowA + 8;
                const float b3v = ((const float*)(smb + B3S_O))[0];
                if (rowA < S_) {
                    float sc = p0 + b3v;
                    if (mA == 0) sc = -1e9f;
                    scf[rowA] = sc;
                }
                if (rowB < S_) {
                    float sc = p8 + b3v;
                    if (mB == 0) sc = -1e9f;
                    scf[rowB] = sc;
                }
            }
            MEMBAR();                 // publish score writes before arrive
            BARRIVE(1 + (it & 1));    // scores(it) ready

        } else {
            // ======== CONSUMER: warps 13-15 (96 threads) ========
            const int tc = t - 416;           // 0..95
            const int cwarp = tc >> 5;        // 0..2
            float* scr = (float*)(smb + SCR_O);

            BSYNC(1 + (it & 1));              // wait scores(it)

            // max
            float v0 = scf[tc];
            float v1 = scf[tc + 96];
            float v2 = (tc < 8) ? scf[tc + 192] : -3e38f;
            float mx = fmaxf(fmaxf(v0, v1), v2);
            #pragma unroll
            for (int o = 16; o; o >>= 1) mx = fmaxf(mx, __shfl_xor_sync(0xffffffffu, mx, o));
            if ((tc & 31) == 0) scr[cwarp] = mx;
            CBAR();
            mx = fmaxf(scr[0], fmaxf(scr[1], scr[2]));

            // exp + sum (scf becomes unnormalized exp)
            const float e0 = __expf(v0 - mx);
            const float e1 = __expf(v1 - mx);
            const float e2 = (tc < 8) ? __expf(v2 - mx) : 0.f;
            scf[tc] = e0;
            scf[tc + 96] = e1;
            if (tc < 8) scf[tc + 192] = e2;
            float ps = e0 + e1 + e2;
            #pragma unroll
            for (int o = 16; o; o >>= 1) ps += __shfl_xor_sync(0xffffffffu, ps, o);
            if ((tc & 31) == 0) scr[3 + cwarp] = ps;
            CBAR();                            // also publishes all exp writes
            const float inv = 1.0f / (scr[3] + scr[4] + scr[5]);

            // weights out
            {
                float* out_w = out + (size_t)B_ * E_ + (size_t)b * S_;
                out_w[tc] = e0 * inv;
                out_w[tc + 96] = e1 * inv;
                if (tc < 8) out_w[tc + 192] = e2 * inv;
            }

            // attended: 3 partitions x ~67 s, float4 keys (L2-hot)
            {
                const int col = tc & 31;      // float4 column
                const float4* kg = (const float4*)(keys + (size_t)b * (S_ * E_)) + col;
                float a0 = 0.f, a1 = 0.f, a2 = 0.f, a3 = 0.f;
                const int sbeg = cwarp * 67;
                const int send = (cwarp == 2) ? S_ : sbeg + 67;
                #pragma unroll 4
                for (int s = sbeg; s < send; ++s) {
                    const float4 kv = kg[(size_t)s * 32];
                    const float w = scf[s];
                    a0 = fmaf(w, kv.x, a0);
                    a1 = fmaf(w, kv.y, a1);
                    a2 = fmaf(w, kv.z, a2);
                    a3 = fmaf(w, kv.w, a3);
                }
                ((float4*)(smb + AP_O))[cwarp * 32 + col] = make_float4(a0, a1, a2, a3);
            }
            CBAR();
            {
                const float* apf = (const float*)(smb + AP_O);
                float* ob = out + (size_t)b * E_;
                {
                    const int e = tc;
                    ob[e] = (apf[e] + apf[128 + e] + apf[256 + e]) * inv;
                }
                if (tc < 32) {
                    const int e = tc + 96;
                    ob[e] = (apf[e] + apf[128 + e] + apf[256 + e]) * inv;
                }
            }
            MEMBAR();                         // order scf reads/AP writes before release
            BARRIVE(3 + (it & 1));            // slot(it) free
        }
    }
}

extern "C" void kernel_launch(void* const* d_in, const int* in_sizes, int n_in,
                              void* d_out, int out_size) {
    const float* query = (const float*)d_in[0];
    const float* keys  = (const float*)d_in[1];
    const int*   mask  = (const int*)d_in[2];
    const float* W1    = (const float*)d_in[3];
    const float* b1    = (const float*)d_in[4];
    const float* W2    = (const float*)d_in[5];
    const float* b2    = (const float*)d_in[6];
    const float* W3    = (const float*)d_in[7];
    const float* b3    = (const float*)d_in[8];
    float* out = (float*)d_out;

    int nsm = 148;
    cudaDeviceGetAttribute(&nsm, cudaDevAttrMultiProcessorCount, 0);
    if (nsm < 112)  nsm = 112;
    if (nsm > 1024) nsm = 1024;

    cudaFuncSetAttribute(attn_persist_kernel,
                         cudaFuncAttributeMaxDynamicSharedMemorySize, SMEM_BYTES);
    attn_persist_kernel<<<nsm, 512, SMEM_BYTES>>>(query, keys, mask, W1, b1, W2, b2, W3, b3, out);
}